// round 1
// baseline (speedup 1.0000x reference)
#include <cuda_runtime.h>
#include <cuda_bf16.h>
#include <math.h>

namespace cfg {
constexpr int B = 2, S = 1024, D = 2048, H = 16, F = 8192, M = 8192;
constexpr int HD = 128, T = B * S;
}

// ---------------- scratch (static __device__ arrays; no allocation) ----------------
__device__ float g_scores[(size_t)cfg::T * cfg::M];   // 64 MB
__device__ int   g_nn[cfg::T];
__device__ float g_merged[(size_t)cfg::T * cfg::D];
__device__ float g_x1[(size_t)cfg::T * cfg::D];
__device__ float g_q[(size_t)cfg::T * cfg::D];
__device__ float g_k[(size_t)cfg::T * cfg::D];
__device__ float g_v[(size_t)cfg::T * cfg::D];
__device__ float g_ctx[(size_t)cfg::T * cfg::D];
__device__ float g_x2[(size_t)cfg::T * cfg::D];
__device__ float g_y[(size_t)cfg::T * cfg::D];
__device__ float g_gate[(size_t)cfg::T * cfg::F];     // 64 MB
__device__ float g_act[(size_t)cfg::T * cfg::F];      // 64 MB

// ---------------- generic 128x128x8 register-tiled SGEMM ----------------
// A: [Mr,K] row-major. TRANSB=0: Bm [K,Nc] rm. TRANSB=1: Bm [Nc,K] rm (B^T).
// EPI: 0 = store, 1 = C = Res + acc, 2 = C = silu(Res) * acc
// All dims: Mr,Nc multiples of 128; K multiple of 8 (guaranteed by shapes).
template<int TRANSB, int EPI>
__global__ __launch_bounds__(256)
void gemm_kernel(const float* __restrict__ A, const float* __restrict__ Bm,
                 const float* __restrict__ Res, float* __restrict__ C,
                 int Mr, int Nc, int K) {
    __shared__ float As[8][128];
    __shared__ float Bs[8][128];
    const int tid  = threadIdx.x;
    const int brow = blockIdx.y * 128;
    const int bcol = blockIdx.x * 128;
    const int tr = (tid >> 4) << 3;   // 0..120
    const int tc = (tid & 15) << 3;

    float acc[8][8];
#pragma unroll
    for (int i = 0; i < 8; i++)
#pragma unroll
        for (int j = 0; j < 8; j++) acc[i][j] = 0.f;

    const int lrow = tid >> 1;          // 0..127
    const int lk   = (tid & 1) << 2;    // 0 or 4
    const float* Ap = A + (size_t)(brow + lrow) * K + lk;
    const float* Bp = TRANSB ? (Bm + (size_t)(bcol + lrow) * K + lk) : nullptr;
    const int bkr = tid >> 5;           // 0..7
    const int bc4 = (tid & 31) << 2;    // 0..124

    for (int k0 = 0; k0 < K; k0 += 8) {
        float4 av = *(const float4*)(Ap + k0);
        As[lk + 0][lrow] = av.x;
        As[lk + 1][lrow] = av.y;
        As[lk + 2][lrow] = av.z;
        As[lk + 3][lrow] = av.w;
        if (TRANSB) {
            float4 bv = *(const float4*)(Bp + k0);
            Bs[lk + 0][lrow] = bv.x;
            Bs[lk + 1][lrow] = bv.y;
            Bs[lk + 2][lrow] = bv.z;
            Bs[lk + 3][lrow] = bv.w;
        } else {
            float4 bv = *(const float4*)(Bm + (size_t)(k0 + bkr) * Nc + bcol + bc4);
            *(float4*)(&Bs[bkr][bc4]) = bv;
        }
        __syncthreads();
#pragma unroll
        for (int kk = 0; kk < 8; kk++) {
            float ra[8], rb[8];
#pragma unroll
            for (int i = 0; i < 8; i++) ra[i] = As[kk][tr + i];
#pragma unroll
            for (int j = 0; j < 8; j++) rb[j] = Bs[kk][tc + j];
#pragma unroll
            for (int i = 0; i < 8; i++)
#pragma unroll
                for (int j = 0; j < 8; j++) acc[i][j] = fmaf(ra[i], rb[j], acc[i][j]);
        }
        __syncthreads();
    }

#pragma unroll
    for (int i = 0; i < 8; i++) {
        size_t ro = (size_t)(brow + tr + i) * Nc + bcol + tc;
#pragma unroll
        for (int j = 0; j < 8; j++) {
            float v = acc[i][j];
            if (EPI == 1) v += Res[ro + j];
            else if (EPI == 2) {
                float gv = Res[ro + j];
                v *= gv / (1.f + __expf(-gv));   // silu(gate) * up
            }
            C[ro + j] = v;
        }
    }
}

// ---------------- argmax over memory scores (first-index tie-break) ----------------
__global__ __launch_bounds__(256)
void argmax_kernel() {
    const int t = blockIdx.x, tid = threadIdx.x;
    const float* row = g_scores + (size_t)t * cfg::M;
    float best = -INFINITY; int bi = 0;
    for (int j = tid; j < cfg::M; j += 256) {
        float v = row[j];
        if (v > best) { best = v; bi = j; }   // ascending scan keeps first max per thread
    }
    __shared__ float sv[256];
    __shared__ int   si[256];
    sv[tid] = best; si[tid] = bi;
    __syncthreads();
    for (int s = 128; s; s >>= 1) {
        if (tid < s) {
            if (sv[tid + s] > sv[tid] ||
                (sv[tid + s] == sv[tid] && si[tid + s] < si[tid])) {
                sv[tid] = sv[tid + s]; si[tid] = si[tid + s];
            }
        }
        __syncthreads();
    }
    if (tid == 0) g_nn[t] = si[0];
}

// ---------------- fused: gather + L2-norm gated mix + RMSNorm1 ----------------
__global__ __launch_bounds__(256)
void merge_rms1_kernel(const float* __restrict__ hs, const float* __restrict__ mem,
                       const float* __restrict__ gatel, const float* __restrict__ r1w) {
    const int t = blockIdx.x, tid = threadIdx.x;
    const float* h = hs + (size_t)t * cfg::D;
    const float* mr = mem + (size_t)g_nn[t] * cfg::D;
    __shared__ float red[256];
    __shared__ float red2[256];
    float sh = 0.f, sm = 0.f;
    for (int d = tid; d < cfg::D; d += 256) {
        float a = h[d], bm = mr[d];
        sh += a * a; sm += bm * bm;
    }
    red[tid] = sh; red2[tid] = sm;
    __syncthreads();
    for (int s = 128; s; s >>= 1) {
        if (tid < s) { red[tid] += red[tid + s]; red2[tid] += red2[tid + s]; }
        __syncthreads();
    }
    const float nh = sqrtf(red[0]) + 1e-4f;   // NORM_EPS
    const float nm = sqrtf(red2[0]) + 1e-4f;
    __syncthreads();

    float s2 = 0.f;
    for (int d = tid; d < cfg::D; d += 256) {
        float g = 1.f / (1.f + __expf(-gatel[d]));
        float mg = (g * h[d] / nh + (1.f - g) * mr[d] / nm) * nh;
        g_merged[(size_t)t * cfg::D + d] = mg;
        s2 += mg * mg;
    }
    red[tid] = s2;
    __syncthreads();
    for (int s = 128; s; s >>= 1) {
        if (tid < s) red[tid] += red[tid + s];
        __syncthreads();
    }
    const float rstd = rsqrtf(red[0] / cfg::D + 1e-6f);  // RMS_EPS
    for (int d = tid; d < cfg::D; d += 256)
        g_x1[(size_t)t * cfg::D + d] = g_merged[(size_t)t * cfg::D + d] * rstd * r1w[d];
}

// ---------------- generic RMSNorm ----------------
__global__ __launch_bounds__(256)
void rmsnorm_kernel(const float* __restrict__ x, const float* __restrict__ w,
                    float* __restrict__ out) {
    const int t = blockIdx.x, tid = threadIdx.x;
    const float* xp = x + (size_t)t * cfg::D;
    __shared__ float red[256];
    float s2 = 0.f;
    for (int d = tid; d < cfg::D; d += 256) { float v = xp[d]; s2 += v * v; }
    red[tid] = s2;
    __syncthreads();
    for (int s = 128; s; s >>= 1) {
        if (tid < s) red[tid] += red[tid + s];
        __syncthreads();
    }
    const float rstd = rsqrtf(red[0] / cfg::D + 1e-6f);
    for (int d = tid; d < cfg::D; d += 256)
        out[(size_t)t * cfg::D + d] = xp[d] * rstd * w[d];
}

// ---------------- RoPE (in-place on q,k) ----------------
__global__ __launch_bounds__(256)
void rope_kernel(const int* __restrict__ pos) {
    const int idx = blockIdx.x * 256 + threadIdx.x;
    if (idx >= cfg::T * cfg::H * 64) return;
    const int i = idx & 63;
    const int h = (idx >> 6) & (cfg::H - 1);
    const int t = idx >> 10;
    const float p = (float)pos[t];
    // inv_freq = 10000^(-i/64) = exp(-i * ln(10000)/64)
    const float inv = expf(-0.14391156831212787f * (float)i);
    float sn, cs;
    sincosf(p * inv, &sn, &cs);
    const size_t base = ((size_t)t * cfg::H + h) * cfg::HD;
    float q1 = g_q[base + i], q2 = g_q[base + i + 64];
    g_q[base + i]      = q1 * cs - q2 * sn;
    g_q[base + i + 64] = q2 * cs + q1 * sn;
    float k1 = g_k[base + i], k2 = g_k[base + i + 64];
    g_k[base + i]      = k1 * cs - k2 * sn;
    g_k[base + i + 64] = k2 * cs + k1 * sn;
}

// ---------------- causal attention: 1 warp per query row, online softmax ----------------
__global__ __launch_bounds__(256)
void attn_kernel() {
    const int tid = threadIdx.x;
    const int warp = tid >> 5, lane = tid & 31;
    const int b = blockIdx.z, h = blockIdx.y;
    const int qrow = blockIdx.x * 8 + warp;
    __shared__ float Ksm[32][128];
    __shared__ float Vsm[32][128];
    const size_t qoff = ((size_t)(b * cfg::S + qrow) * cfg::H + h) * cfg::HD;
    float qf[4];
#pragma unroll
    for (int i = 0; i < 4; i++) qf[i] = g_q[qoff + lane + 32 * i];
    float m = -INFINITY, l = 0.f;
    float acc[4] = {0.f, 0.f, 0.f, 0.f};
    const int nk = blockIdx.x * 8 + 8;   // keys needed by deepest row in block
    const float scale = 0.08838834764831845f;  // 1/sqrt(128)

    for (int s0 = 0; s0 < nk; s0 += 32) {
        __syncthreads();
        for (int i = tid; i < 32 * 128; i += 256) {
            int r = i >> 7, c = i & 127;
            size_t off = ((size_t)(b * cfg::S + s0 + r) * cfg::H + h) * cfg::HD + c;
            Ksm[r][c] = g_k[off];
            Vsm[r][c] = g_v[off];
        }
        __syncthreads();
        const int lim = min(32, qrow + 1 - s0);
        for (int kk = 0; kk < lim; kk++) {
            float p = qf[0] * Ksm[kk][lane]      + qf[1] * Ksm[kk][lane + 32] +
                      qf[2] * Ksm[kk][lane + 64] + qf[3] * Ksm[kk][lane + 96];
#pragma unroll
            for (int o = 16; o; o >>= 1) p += __shfl_xor_sync(0xffffffffu, p, o);
            p *= scale;
            float mn = fmaxf(m, p);
            float corr = __expf(m - mn);
            float w = __expf(p - mn);
            l = l * corr + w;
#pragma unroll
            for (int i = 0; i < 4; i++) acc[i] = acc[i] * corr + w * Vsm[kk][lane + 32 * i];
            m = mn;
        }
    }
    const float inv = 1.f / l;
#pragma unroll
    for (int i = 0; i < 4; i++) g_ctx[qoff + lane + 32 * i] = acc[i] * inv;
}

// ---------------- launch ----------------
extern "C" void kernel_launch(void* const* d_in, const int* in_sizes, int n_in,
                              void* d_out, int out_size) {
    const float* hs    = (const float*)d_in[0];
    const int*   pos   = (const int*)d_in[1];
    const float* mem   = (const float*)d_in[2];
    const float* gatel = (const float*)d_in[3];
    const float* wq    = (const float*)d_in[4];
    const float* wk    = (const float*)d_in[5];
    const float* wv    = (const float*)d_in[6];
    const float* wo    = (const float*)d_in[7];
    const float* wg    = (const float*)d_in[8];
    const float* wu    = (const float*)d_in[9];
    const float* wd    = (const float*)d_in[10];
    const float* r1w   = (const float*)d_in[11];
    const float* r2w   = (const float*)d_in[12];
    float* out = (float*)d_out;

    float *p_scores, *p_merged, *p_x1, *p_q, *p_k, *p_v, *p_ctx, *p_x2, *p_y, *p_g, *p_act;
    cudaGetSymbolAddress((void**)&p_scores, g_scores);
    cudaGetSymbolAddress((void**)&p_merged, g_merged);
    cudaGetSymbolAddress((void**)&p_x1, g_x1);
    cudaGetSymbolAddress((void**)&p_q, g_q);
    cudaGetSymbolAddress((void**)&p_k, g_k);
    cudaGetSymbolAddress((void**)&p_v, g_v);
    cudaGetSymbolAddress((void**)&p_ctx, g_ctx);
    cudaGetSymbolAddress((void**)&p_x2, g_x2);
    cudaGetSymbolAddress((void**)&p_y, g_y);
    cudaGetSymbolAddress((void**)&p_g, g_gate);
    cudaGetSymbolAddress((void**)&p_act, g_act);

    const dim3 blk(256);

    // 1) kNN scores (NT GEMM) + argmax
    gemm_kernel<1, 0><<<dim3(cfg::M / 128, cfg::T / 128), blk>>>(
        hs, mem, nullptr, p_scores, cfg::T, cfg::M, cfg::D);
    argmax_kernel<<<cfg::T, blk>>>();

    // 2) gated merge + RMSNorm1 (fused)
    merge_rms1_kernel<<<cfg::T, blk>>>(hs, mem, gatel, r1w);

    // 3) Q/K/V projections
    gemm_kernel<0, 0><<<dim3(cfg::D / 128, cfg::T / 128), blk>>>(
        p_x1, wq, nullptr, p_q, cfg::T, cfg::D, cfg::D);
    gemm_kernel<0, 0><<<dim3(cfg::D / 128, cfg::T / 128), blk>>>(
        p_x1, wk, nullptr, p_k, cfg::T, cfg::D, cfg::D);
    gemm_kernel<0, 0><<<dim3(cfg::D / 128, cfg::T / 128), blk>>>(
        p_x1, wv, nullptr, p_v, cfg::T, cfg::D, cfg::D);

    // 4) RoPE
    rope_kernel<<<(cfg::T * cfg::H * 64 + 255) / 256, blk>>>(pos);

    // 5) causal attention
    attn_kernel<<<dim3(cfg::S / 8, cfg::H, cfg::B), blk>>>();

    // 6) O projection + residual (residual = merged)
    gemm_kernel<0, 1><<<dim3(cfg::D / 128, cfg::T / 128), blk>>>(
        p_ctx, wo, p_merged, p_x2, cfg::T, cfg::D, cfg::D);

    // 7) RMSNorm2
    rmsnorm_kernel<<<cfg::T, blk>>>(p_x2, r2w, p_y);

    // 8) MLP: gate, up (fused silu*up epilogue), down (+residual) -> d_out
    gemm_kernel<0, 0><<<dim3(cfg::F / 128, cfg::T / 128), blk>>>(
        p_y, wg, nullptr, p_g, cfg::T, cfg::F, cfg::D);
    gemm_kernel<0, 2><<<dim3(cfg::F / 128, cfg::T / 128), blk>>>(
        p_y, wu, p_g, p_act, cfg::T, cfg::F, cfg::D);
    gemm_kernel<0, 1><<<dim3(cfg::D / 128, cfg::T / 128), blk>>>(
        p_act, wd, p_x2, out, cfg::T, cfg::D, cfg::F);
}

// round 3
// speedup vs baseline: 2.4849x; 2.4849x over previous
#include <cuda_runtime.h>
#include <cuda_bf16.h>
#include <cstdint>
#include <math.h>

namespace cfg {
constexpr int B = 2, S = 1024, D = 2048, H = 16, F = 8192, M = 8192;
constexpr int HD = 128, T = B * S;
}
using bf16 = __nv_bfloat16;

// ==================== scratch (static __device__; no allocation) ====================
__device__ unsigned long long g_nnpack[cfg::T];
__device__ float g_merged[(size_t)cfg::T * cfg::D];
__device__ float g_qkv[(size_t)cfg::T * 3 * cfg::D];
__device__ float g_x2[(size_t)cfg::T * cfg::D];
__device__ float g_gate[(size_t)cfg::T * cfg::F];
// split activations (bf16 hi/lo)
__device__ bf16 g_hs_h[(size_t)cfg::T * cfg::D],  g_hs_l[(size_t)cfg::T * cfg::D];
__device__ bf16 g_x1_h[(size_t)cfg::T * cfg::D],  g_x1_l[(size_t)cfg::T * cfg::D];
__device__ bf16 g_ctx_h[(size_t)cfg::T * cfg::D], g_ctx_l[(size_t)cfg::T * cfg::D];
__device__ bf16 g_y_h[(size_t)cfg::T * cfg::D],   g_y_l[(size_t)cfg::T * cfg::D];
__device__ bf16 g_act_h[(size_t)cfg::T * cfg::F], g_act_l[(size_t)cfg::T * cfg::F];
// split weights, [N,K] row-major bf16 hi/lo
__device__ bf16 g_wqkv_h[(size_t)3 * cfg::D * cfg::D], g_wqkv_l[(size_t)3 * cfg::D * cfg::D];
__device__ bf16 g_wo_h[(size_t)cfg::D * cfg::D],       g_wo_l[(size_t)cfg::D * cfg::D];
__device__ bf16 g_wg_h[(size_t)cfg::D * cfg::F],       g_wg_l[(size_t)cfg::D * cfg::F];
__device__ bf16 g_wu_h[(size_t)cfg::D * cfg::F],       g_wu_l[(size_t)cfg::D * cfg::F];
__device__ bf16 g_wd_h[(size_t)cfg::F * cfg::D],       g_wd_l[(size_t)cfg::F * cfg::D];
__device__ bf16 g_mem_h[(size_t)cfg::M * cfg::D],      g_mem_l[(size_t)cfg::M * cfg::D];

// ==================== helpers ====================
__device__ __forceinline__ uint32_t smem_u32(const void* p) {
    uint32_t a;
    asm("{ .reg .u64 t; cvta.to.shared.u64 t, %1; cvt.u32.u64 %0, t; }" : "=r"(a) : "l"(p));
    return a;
}
__device__ __forceinline__ uint32_t fmono(float f) {
    uint32_t u = __float_as_uint(f);
    return (u & 0x80000000u) ? ~u : (u | 0x80000000u);
}
__device__ __forceinline__ void split1(float x, bf16& h, bf16& l) {
    h = __float2bfloat16(x);
    l = __float2bfloat16(x - __bfloat162float(h));
}

#define CP16(d, s) asm volatile("cp.async.cg.shared.global [%0], [%1], 16;" :: "r"(d), "l"(s) : "memory")
#define CPCOMMIT() asm volatile("cp.async.commit_group;" ::: "memory")
#define CPWAIT1()  asm volatile("cp.async.wait_group 1;" ::: "memory")
#define CPWAIT0()  asm volatile("cp.async.wait_group 0;" ::: "memory")
#define LDSM4(r, a)                                                              \
    asm volatile("ldmatrix.sync.aligned.m8n8.x4.shared.b16 {%0,%1,%2,%3}, [%4];" \
        : "=r"((r)[0]), "=r"((r)[1]), "=r"((r)[2]), "=r"((r)[3]) : "r"(a))
#define MMA(c, a, b0, b1)                                                        \
    asm volatile("mma.sync.aligned.m16n8k16.row.col.f32.bf16.bf16.f32 "          \
        "{%0,%1,%2,%3},{%4,%5,%6,%7},{%8,%9},{%0,%1,%2,%3};"                     \
        : "+f"((c)[0]), "+f"((c)[1]), "+f"((c)[2]), "+f"((c)[3])                 \
        : "r"((a)[0]), "r"((a)[1]), "r"((a)[2]), "r"((a)[3]), "r"(b0), "r"(b1))

// ==================== split-bf16 3-pass mma.sync GEMM ====================
// C[128x128 tile] = (Ah+Al)[M,K] @ (Bh+Bl)[N,K]^T, dropping Al*Bl.
// Tiles in smem: 128 rows x 32 k bf16, 80-byte padded rows (conflict-free).
// EPI: 0 store fp32, 1 C=Res+acc fp32, 2 Ch/Cl = split(silu(Res)*acc), 3 row-argmax.
constexpr int ROWB = 80;                 // padded row stride bytes (32 bf16 = 64B data)
constexpr int TILEB = 128 * ROWB;        // 10240
constexpr int STAGEB = 4 * TILEB;        // 40960
constexpr int GEMM_SMEM = 2 * STAGEB;    // 81920

template<int EPI>
__global__ __launch_bounds__(256, 2)
void gemm_tc(const bf16* __restrict__ Ah_, const bf16* __restrict__ Al_,
             const bf16* __restrict__ Bh_, const bf16* __restrict__ Bl_,
             const float* __restrict__ Res, float* __restrict__ C,
             bf16* __restrict__ Ch, bf16* __restrict__ Cl,
             unsigned long long* __restrict__ argout, int Nc, int K) {
    extern __shared__ char dsm[];
    const uint32_t sb = smem_u32(dsm);
    const int tid = threadIdx.x, lane = tid & 31, warp = tid >> 5;
    const int wm = warp & 3, wn = warp >> 2;
    const int brow = blockIdx.y << 7, bcol = blockIdx.x << 7;

    // ---- cp.async source pointers (thread -> 2 rows x 1 seg per tile) ----
    const int r0 = tid >> 2, sg = tid & 3;
    const size_t rowK = (size_t)K * sizeof(bf16);
    const char* gAh = (const char*)Ah_ + (size_t)(brow + r0) * rowK + sg * 16;
    const char* gAl = (const char*)Al_ + (size_t)(brow + r0) * rowK + sg * 16;
    const char* gBh = (const char*)Bh_ + (size_t)(bcol + r0) * rowK + sg * 16;
    const char* gBl = (const char*)Bl_ + (size_t)(bcol + r0) * rowK + sg * 16;
    const size_t half = 64 * rowK;
    const uint32_t d0 = (uint32_t)(r0 * ROWB + sg * 16), d1 = d0 + 64 * ROWB;

#define ISSUE(ch) do {                                                           \
    uint32_t sd = sb + (((ch) & 1) ? STAGEB : 0);                                \
    size_t go = (size_t)(ch) * 64;                                               \
    CP16(sd + d0,             gAh + go); CP16(sd + d1,             gAh + half + go); \
    CP16(sd + TILEB + d0,     gAl + go); CP16(sd + TILEB + d1,     gAl + half + go); \
    CP16(sd + 2 * TILEB + d0, gBh + go); CP16(sd + 2 * TILEB + d1, gBh + half + go); \
    CP16(sd + 3 * TILEB + d0, gBl + go); CP16(sd + 3 * TILEB + d1, gBl + half + go); \
    CPCOMMIT();                                                                  \
} while (0)

    // ---- ldmatrix lane offsets ----
    // A x4: lanes 0-7 m0-7/k0, 8-15 m8-15/k0, 16-23 m0-7/k8, 24-31 m8-15/k8
    const uint32_t aOff = (uint32_t)((wm * 32 + (lane & 15)) * ROWB + (lane >> 4) * 16);
    // B x4: lanes 0-7 n0-7/k0, 8-15 n0-7/k8, 16-23 n8-15/k0, 24-31 n8-15/k8
    const uint32_t bOff = (uint32_t)((wn * 64 + ((lane >> 4) << 3) + (lane & 7)) * ROWB +
                                     ((lane >> 3) & 1) * 16);

    float acc[64];
#pragma unroll
    for (int i = 0; i < 64; i++) acc[i] = 0.f;

    const int nch = K >> 5;
    ISSUE(0);
    for (int ch = 0; ch < nch; ch++) {
        if (ch + 1 < nch) { ISSUE(ch + 1); CPWAIT1(); }
        else CPWAIT0();
        __syncthreads();
        const uint32_t bb = sb + ((ch & 1) ? STAGEB : 0);
#pragma unroll
        for (int ks = 0; ks < 2; ks++) {
            const uint32_t ko = ks * 32;
            uint32_t ah[2][4], al[2][4];
            LDSM4(ah[0], bb + aOff + ko);
            LDSM4(ah[1], bb + aOff + 1280 + ko);          // mf=1: +16 rows
            LDSM4(al[0], bb + TILEB + aOff + ko);
            LDSM4(al[1], bb + TILEB + aOff + 1280 + ko);
#pragma unroll
            for (int np = 0; np < 4; np++) {
                uint32_t bh[4], bl[4];
                LDSM4(bh, bb + 2 * TILEB + bOff + np * 1280 + ko);
                LDSM4(bl, bb + 3 * TILEB + bOff + np * 1280 + ko);
                float* c00 = acc + (0 * 8 + np * 2) * 4;
                float* c01 = acc + (0 * 8 + np * 2 + 1) * 4;
                float* c10 = acc + (1 * 8 + np * 2) * 4;
                float* c11 = acc + (1 * 8 + np * 2 + 1) * 4;
                MMA(c00, ah[0], bh[0], bh[1]); MMA(c01, ah[0], bh[2], bh[3]);
                MMA(c10, ah[1], bh[0], bh[1]); MMA(c11, ah[1], bh[2], bh[3]);
                MMA(c00, ah[0], bl[0], bl[1]); MMA(c01, ah[0], bl[2], bl[3]);
                MMA(c10, ah[1], bl[0], bl[1]); MMA(c11, ah[1], bl[2], bl[3]);
                MMA(c00, al[0], bh[0], bh[1]); MMA(c01, al[0], bh[2], bh[3]);
                MMA(c10, al[1], bh[0], bh[1]); MMA(c11, al[1], bh[2], bh[3]);
            }
        }
        __syncthreads();
    }
#undef ISSUE

    // ---- epilogue ----
    const int rq = lane >> 2, cp2 = (lane & 3) * 2;
    if (EPI == 3) {
#pragma unroll
        for (int mf = 0; mf < 2; mf++)
#pragma unroll
        for (int hh = 0; hh < 2; hh++) {
            const int row = brow + wm * 32 + mf * 16 + rq + hh * 8;
            float best = -3.4e38f; int bi = 0;
#pragma unroll
            for (int nf = 0; nf < 8; nf++)
#pragma unroll
            for (int c = 0; c < 2; c++) {
                float v = acc[(mf * 8 + nf) * 4 + hh * 2 + c];
                int col = bcol + wn * 64 + nf * 8 + cp2 + c;
                if (v > best) { best = v; bi = col; }
            }
            unsigned long long pk =
                ((unsigned long long)fmono(best) << 32) | (uint32_t)(~(uint32_t)bi);
            unsigned long long o1 = __shfl_xor_sync(0xffffffffu, pk, 1); if (o1 > pk) pk = o1;
            unsigned long long o2 = __shfl_xor_sync(0xffffffffu, pk, 2); if (o2 > pk) pk = o2;
            if ((lane & 3) == 0) atomicMax(argout + row, pk);
        }
    } else {
#pragma unroll
        for (int mf = 0; mf < 2; mf++)
#pragma unroll
        for (int hh = 0; hh < 2; hh++) {
            const int row = brow + wm * 32 + mf * 16 + rq + hh * 8;
            const size_t ro = (size_t)row * Nc + bcol + wn * 64 + cp2;
#pragma unroll
            for (int nf = 0; nf < 8; nf++) {
                const size_t o = ro + nf * 8;
                float v0 = acc[(mf * 8 + nf) * 4 + hh * 2];
                float v1 = acc[(mf * 8 + nf) * 4 + hh * 2 + 1];
                if (EPI == 1) {
                    float2 rr = *(const float2*)(Res + o);
                    v0 += rr.x; v1 += rr.y;
                    *(float2*)(C + o) = make_float2(v0, v1);
                } else if (EPI == 2) {
                    float2 g = *(const float2*)(Res + o);
                    v0 *= g.x / (1.f + __expf(-g.x));
                    v1 *= g.y / (1.f + __expf(-g.y));
                    bf16 h0, l0, h1, l1;
                    split1(v0, h0, l0); split1(v1, h1, l1);
                    *(__nv_bfloat162*)(Ch + o) = __halves2bfloat162(h0, h1);
                    *(__nv_bfloat162*)(Cl + o) = __halves2bfloat162(l0, l1);
                } else {
                    *(float2*)(C + o) = make_float2(v0, v1);
                }
            }
        }
    }
}

// ==================== weight transpose + split ([K,N] fp32 -> [N,K] bf16 hi/lo) ====================
__global__ __launch_bounds__(256)
void transpose_split(const float* __restrict__ W, bf16* __restrict__ Oh,
                     bf16* __restrict__ Ol, int K, int N) {
    __shared__ float t[32][33];
    const int n0 = blockIdx.x * 32, k0 = blockIdx.y * 32;
    const int tx = threadIdx.x & 31, ty = threadIdx.x >> 5;
#pragma unroll
    for (int j = 0; j < 32; j += 8)
        t[ty + j][tx] = W[(size_t)(k0 + ty + j) * N + n0 + tx];
    __syncthreads();
#pragma unroll
    for (int j = 0; j < 32; j += 8) {
        float v = t[tx][ty + j];
        size_t o = (size_t)(n0 + ty + j) * K + k0 + tx;
        split1(v, Oh[o], Ol[o]);
    }
}

__global__ __launch_bounds__(256)
void split_only(const float* __restrict__ W, bf16* __restrict__ Oh,
                bf16* __restrict__ Ol, size_t n4) {
    size_t i = (size_t)blockIdx.x * 256 + threadIdx.x;
    if (i >= n4) return;
    float4 v = ((const float4*)W)[i];
    bf16 h0, l0, h1, l1, h2, l2, h3, l3;
    split1(v.x, h0, l0); split1(v.y, h1, l1);
    split1(v.z, h2, l2); split1(v.w, h3, l3);
    __nv_bfloat162 H0 = __halves2bfloat162(h0, h1), H1 = __halves2bfloat162(h2, h3);
    __nv_bfloat162 L0 = __halves2bfloat162(l0, l1), L1 = __halves2bfloat162(l2, l3);
    ((uint2*)Oh)[i] = make_uint2(*(uint32_t*)&H0, *(uint32_t*)&H1);
    ((uint2*)Ol)[i] = make_uint2(*(uint32_t*)&L0, *(uint32_t*)&L1);
}

__global__ void init_argmax() {
    int i = blockIdx.x * 256 + threadIdx.x;
    if (i < cfg::T) g_nnpack[i] = 0ull;
}

// ==================== fused gather + gated L2 mix + RMSNorm1 (-> x1 hi/lo) ====================
__global__ __launch_bounds__(256)
void merge_rms1_kernel(const float* __restrict__ hs, const float* __restrict__ mem,
                       const float* __restrict__ gatel, const float* __restrict__ r1w) {
    const int t = blockIdx.x, tid = threadIdx.x;
    const uint32_t idx = ~(uint32_t)(g_nnpack[t] & 0xffffffffull);
    const float* h = hs + (size_t)t * cfg::D;
    const float* mr = mem + (size_t)idx * cfg::D;
    __shared__ float red[256], red2[256];
    float sh = 0.f, sm = 0.f;
    for (int d = tid; d < cfg::D; d += 256) {
        float a = h[d], bm = mr[d];
        sh += a * a; sm += bm * bm;
    }
    red[tid] = sh; red2[tid] = sm;
    __syncthreads();
    for (int s = 128; s; s >>= 1) {
        if (tid < s) { red[tid] += red[tid + s]; red2[tid] += red2[tid + s]; }
        __syncthreads();
    }
    const float nh = sqrtf(red[0]) + 1e-4f;
    const float nm = sqrtf(red2[0]) + 1e-4f;
    __syncthreads();
    float s2 = 0.f;
    for (int d = tid; d < cfg::D; d += 256) {
        float g = 1.f / (1.f + __expf(-gatel[d]));
        float mg = (g * h[d] / nh + (1.f - g) * mr[d] / nm) * nh;
        g_merged[(size_t)t * cfg::D + d] = mg;
        s2 += mg * mg;
    }
    red[tid] = s2;
    __syncthreads();
    for (int s = 128; s; s >>= 1) {
        if (tid < s) red[tid] += red[tid + s];
        __syncthreads();
    }
    const float rstd = rsqrtf(red[0] / cfg::D + 1e-6f);
    for (int d = tid; d < cfg::D; d += 256) {
        float v = g_merged[(size_t)t * cfg::D + d] * rstd * r1w[d];
        size_t o = (size_t)t * cfg::D + d;
        split1(v, g_x1_h[o], g_x1_l[o]);
    }
}

// ==================== RMSNorm2 (-> y hi/lo) ====================
__global__ __launch_bounds__(256)
void rmsnorm_kernel(const float* __restrict__ x, const float* __restrict__ w) {
    const int t = blockIdx.x, tid = threadIdx.x;
    const float* xp = x + (size_t)t * cfg::D;
    __shared__ float red[256];
    float s2 = 0.f;
    for (int d = tid; d < cfg::D; d += 256) { float v = xp[d]; s2 += v * v; }
    red[tid] = s2;
    __syncthreads();
    for (int s = 128; s; s >>= 1) {
        if (tid < s) red[tid] += red[tid + s];
        __syncthreads();
    }
    const float rstd = rsqrtf(red[0] / cfg::D + 1e-6f);
    for (int d = tid; d < cfg::D; d += 256) {
        float v = xp[d] * rstd * w[d];
        size_t o = (size_t)t * cfg::D + d;
        split1(v, g_y_h[o], g_y_l[o]);
    }
}

// ==================== RoPE (in-place on qkv [T, 3D]) ====================
__global__ __launch_bounds__(256)
void rope_kernel(const int* __restrict__ pos) {
    const int idx = blockIdx.x * 256 + threadIdx.x;
    if (idx >= cfg::T * cfg::H * 64) return;
    const int i = idx & 63;
    const int h = (idx >> 6) & (cfg::H - 1);
    const int t = idx >> 10;
    const float p = (float)pos[t];
    const float inv = expf(-0.14391156831212787f * (float)i);
    float sn, cs;
    sincosf(p * inv, &sn, &cs);
    const size_t base = (size_t)t * (3 * cfg::D) + h * cfg::HD;
    float q1 = g_qkv[base + i], q2 = g_qkv[base + i + 64];
    g_qkv[base + i]      = q1 * cs - q2 * sn;
    g_qkv[base + i + 64] = q2 * cs + q1 * sn;
    const size_t kb = base + cfg::D;
    float k1 = g_qkv[kb + i], k2 = g_qkv[kb + i + 64];
    g_qkv[kb + i]      = k1 * cs - k2 * sn;
    g_qkv[kb + i + 64] = k2 * cs + k1 * sn;
}

// ==================== causal attention (warp per q-row) -> ctx hi/lo ====================
__global__ __launch_bounds__(256)
void attn_kernel() {
    const int tid = threadIdx.x;
    const int warp = tid >> 5, lane = tid & 31;
    const int b = blockIdx.z, h = blockIdx.y;
    const int qrow = blockIdx.x * 8 + warp;
    __shared__ float Ksm[32][128];
    __shared__ float Vsm[32][128];
    const size_t qb = (size_t)(b * cfg::S + qrow) * (3 * cfg::D) + h * cfg::HD;
    float qf[4];
#pragma unroll
    for (int i = 0; i < 4; i++) qf[i] = g_qkv[qb + lane + 32 * i];
    float m = -INFINITY, l = 0.f;
    float acc[4] = {0.f, 0.f, 0.f, 0.f};
    const int nk = blockIdx.x * 8 + 8;
    const float scale = 0.08838834764831845f;

    for (int s0 = 0; s0 < nk; s0 += 32) {
        __syncthreads();
        for (int i = tid; i < 32 * 128; i += 256) {
            int r = i >> 7, c = i & 127;
            size_t off = (size_t)(b * cfg::S + s0 + r) * (3 * cfg::D) + h * cfg::HD + c;
            Ksm[r][c] = g_qkv[off + cfg::D];
            Vsm[r][c] = g_qkv[off + 2 * cfg::D];
        }
        __syncthreads();
        const int lim = min(32, qrow + 1 - s0);
        for (int kk = 0; kk < lim; kk++) {
            float p = qf[0] * Ksm[kk][lane]      + qf[1] * Ksm[kk][lane + 32] +
                      qf[2] * Ksm[kk][lane + 64] + qf[3] * Ksm[kk][lane + 96];
#pragma unroll
            for (int o = 16; o; o >>= 1) p += __shfl_xor_sync(0xffffffffu, p, o);
            p *= scale;
            float mn = fmaxf(m, p);
            float corr = __expf(m - mn);
            float w = __expf(p - mn);
            l = l * corr + w;
#pragma unroll
            for (int i = 0; i < 4; i++) acc[i] = acc[i] * corr + w * Vsm[kk][lane + 32 * i];
            m = mn;
        }
    }
    const float inv = 1.f / l;
    const size_t ob = (size_t)(b * cfg::S + qrow) * cfg::D + h * cfg::HD;
#pragma unroll
    for (int i = 0; i < 4; i++) {
        float v = acc[i] * inv;
        split1(v, g_ctx_h[ob + lane + 32 * i], g_ctx_l[ob + lane + 32 * i]);
    }
}

// ==================== launch ====================
extern "C" void kernel_launch(void* const* d_in, const int* in_sizes, int n_in,
                              void* d_out, int out_size) {
    using namespace cfg;
    const float* hs    = (const float*)d_in[0];
    const int*   pos   = (const int*)d_in[1];
    const float* mem   = (const float*)d_in[2];
    const float* gatel = (const float*)d_in[3];
    const float* wq    = (const float*)d_in[4];
    const float* wk    = (const float*)d_in[5];
    const float* wv    = (const float*)d_in[6];
    const float* wo    = (const float*)d_in[7];
    const float* wg    = (const float*)d_in[8];
    const float* wu    = (const float*)d_in[9];
    const float* wd    = (const float*)d_in[10];
    const float* r1w   = (const float*)d_in[11];
    const float* r2w   = (const float*)d_in[12];
    float* out = (float*)d_out;

    static bool attr_set = false;
    if (!attr_set) {
        cudaFuncSetAttribute(gemm_tc<0>, cudaFuncAttributeMaxDynamicSharedMemorySize, GEMM_SMEM);
        cudaFuncSetAttribute(gemm_tc<1>, cudaFuncAttributeMaxDynamicSharedMemorySize, GEMM_SMEM);
        cudaFuncSetAttribute(gemm_tc<2>, cudaFuncAttributeMaxDynamicSharedMemorySize, GEMM_SMEM);
        cudaFuncSetAttribute(gemm_tc<3>, cudaFuncAttributeMaxDynamicSharedMemorySize, GEMM_SMEM);
        attr_set = true;
    }

    float *p_merged, *p_qkv, *p_x2, *p_gate;
    unsigned long long* p_nn;
    bf16 *p_hs_h, *p_hs_l, *p_x1_h, *p_x1_l, *p_ctx_h, *p_ctx_l, *p_y_h, *p_y_l;
    bf16 *p_act_h, *p_act_l;
    bf16 *p_wqkv_h, *p_wqkv_l, *p_wo_h, *p_wo_l, *p_wg_h, *p_wg_l;
    bf16 *p_wu_h, *p_wu_l, *p_wd_h, *p_wd_l, *p_mem_h, *p_mem_l;
    cudaGetSymbolAddress((void**)&p_merged, g_merged);
    cudaGetSymbolAddress((void**)&p_qkv, g_qkv);
    cudaGetSymbolAddress((void**)&p_x2, g_x2);
    cudaGetSymbolAddress((void**)&p_gate, g_gate);
    cudaGetSymbolAddress((void**)&p_nn, g_nnpack);
    cudaGetSymbolAddress((void**)&p_hs_h, g_hs_h);
    cudaGetSymbolAddress((void**)&p_hs_l, g_hs_l);
    cudaGetSymbolAddress((void**)&p_x1_h, g_x1_h);
    cudaGetSymbolAddress((void**)&p_x1_l, g_x1_l);
    cudaGetSymbolAddress((void**)&p_ctx_h, g_ctx_h);
    cudaGetSymbolAddress((void**)&p_ctx_l, g_ctx_l);
    cudaGetSymbolAddress((void**)&p_y_h, g_y_h);
    cudaGetSymbolAddress((void**)&p_y_l, g_y_l);
    cudaGetSymbolAddress((void**)&p_act_h, g_act_h);
    cudaGetSymbolAddress((void**)&p_act_l, g_act_l);
    cudaGetSymbolAddress((void**)&p_wqkv_h, g_wqkv_h);
    cudaGetSymbolAddress((void**)&p_wqkv_l, g_wqkv_l);
    cudaGetSymbolAddress((void**)&p_wo_h, g_wo_h);
    cudaGetSymbolAddress((void**)&p_wo_l, g_wo_l);
    cudaGetSymbolAddress((void**)&p_wg_h, g_wg_h);
    cudaGetSymbolAddress((void**)&p_wg_l, g_wg_l);
    cudaGetSymbolAddress((void**)&p_wu_h, g_wu_h);
    cudaGetSymbolAddress((void**)&p_wu_l, g_wu_l);
    cudaGetSymbolAddress((void**)&p_wd_h, g_wd_h);
    cudaGetSymbolAddress((void**)&p_wd_l, g_wd_l);
    cudaGetSymbolAddress((void**)&p_mem_h, g_mem_h);
    cudaGetSymbolAddress((void**)&p_mem_l, g_mem_l);

    const dim3 blk(256);

    // ---- prep: weight transpose+split, activation splits ----
    transpose_split<<<dim3(D / 32, D / 32), blk>>>(wq, p_wqkv_h, p_wqkv_l, D, D);
    transpose_split<<<dim3(D / 32, D / 32), blk>>>(wk, p_wqkv_h + (size_t)D * D,
                                                   p_wqkv_l + (size_t)D * D, D, D);
    transpose_split<<<dim3(D / 32, D / 32), blk>>>(wv, p_wqkv_h + 2 * (size_t)D * D,
                                                   p_wqkv_l + 2 * (size_t)D * D, D, D);
    transpose_split<<<dim3(D / 32, D / 32), blk>>>(wo, p_wo_h, p_wo_l, D, D);
    transpose_split<<<dim3(F / 32, D / 32), blk>>>(wg, p_wg_h, p_wg_l, D, F);
    transpose_split<<<dim3(F / 32, D / 32), blk>>>(wu, p_wu_h, p_wu_l, D, F);
    transpose_split<<<dim3(D / 32, F / 32), blk>>>(wd, p_wd_h, p_wd_l, F, D);
    split_only<<<((size_t)M * D / 4 + 255) / 256, blk>>>(mem, p_mem_h, p_mem_l, (size_t)M * D / 4);
    split_only<<<((size_t)T * D / 4 + 255) / 256, blk>>>(hs, p_hs_h, p_hs_l, (size_t)T * D / 4);
    init_argmax<<<(T + 255) / 256, blk>>>();

    // ---- 1) kNN scores GEMM with fused argmax ----
    gemm_tc<3><<<dim3(M / 128, T / 128), blk, GEMM_SMEM>>>(
        p_hs_h, p_hs_l, p_mem_h, p_mem_l, nullptr, nullptr, nullptr, nullptr, p_nn, M, D);

    // ---- 2) gated merge + RMSNorm1 -> x1 hi/lo ----
    merge_rms1_kernel<<<T, blk>>>(hs, mem, gatel, r1w);

    // ---- 3) fused QKV projection [T, 3D] fp32 ----
    gemm_tc<0><<<dim3(3 * D / 128, T / 128), blk, GEMM_SMEM>>>(
        p_x1_h, p_x1_l, p_wqkv_h, p_wqkv_l, nullptr, p_qkv, nullptr, nullptr, nullptr, 3 * D, D);

    // ---- 4) RoPE ----
    rope_kernel<<<(T * H * 64 + 255) / 256, blk>>>(pos);

    // ---- 5) causal attention -> ctx hi/lo ----
    attn_kernel<<<dim3(S / 8, H, B), blk>>>();

    // ---- 6) O projection + residual -> x2 fp32 ----
    gemm_tc<1><<<dim3(D / 128, T / 128), blk, GEMM_SMEM>>>(
        p_ctx_h, p_ctx_l, p_wo_h, p_wo_l, p_merged, p_x2, nullptr, nullptr, nullptr, D, D);

    // ---- 7) RMSNorm2 -> y hi/lo ----
    rmsnorm_kernel<<<T, blk>>>(p_x2, r2w);

    // ---- 8) MLP: gate fp32; up w/ silu epi -> act hi/lo; down + residual -> out ----
    gemm_tc<0><<<dim3(F / 128, T / 128), blk, GEMM_SMEM>>>(
        p_y_h, p_y_l, p_wg_h, p_wg_l, nullptr, p_gate, nullptr, nullptr, nullptr, F, D);
    gemm_tc<2><<<dim3(F / 128, T / 128), blk, GEMM_SMEM>>>(
        p_y_h, p_y_l, p_wu_h, p_wu_l, p_gate, nullptr, p_act_h, p_act_l, nullptr, F, D);
    gemm_tc<1><<<dim3(D / 128, T / 128), blk, GEMM_SMEM>>>(
        p_act_h, p_act_l, p_wd_h, p_wd_l, p_x2, out, nullptr, nullptr, nullptr, D, F);
}

// round 4
// speedup vs baseline: 2.6582x; 1.0697x over previous
#include <cuda_runtime.h>
#include <cuda_bf16.h>
#include <cstdint>
#include <math.h>

namespace cfg {
constexpr int B = 2, S = 1024, D = 2048, H = 16, F = 8192, M = 8192;
constexpr int HD = 128, T = B * S;
}
using bf16 = __nv_bfloat16;

// ==================== scratch (static __device__; no allocation) ====================
__device__ unsigned long long g_nnpack[cfg::T];
__device__ float g_merged[(size_t)cfg::T * cfg::D];
__device__ float g_qkv[(size_t)cfg::T * 3 * cfg::D];
__device__ float g_x2[(size_t)cfg::T * cfg::D];
__device__ float g_gate[(size_t)cfg::T * cfg::F];
// split activations (bf16 hi/lo)
__device__ bf16 g_hs_h[(size_t)cfg::T * cfg::D],  g_hs_l[(size_t)cfg::T * cfg::D];
__device__ bf16 g_x1_h[(size_t)cfg::T * cfg::D],  g_x1_l[(size_t)cfg::T * cfg::D];
__device__ bf16 g_ctx_h[(size_t)cfg::T * cfg::D], g_ctx_l[(size_t)cfg::T * cfg::D];
__device__ bf16 g_y_h[(size_t)cfg::T * cfg::D],   g_y_l[(size_t)cfg::T * cfg::D];
__device__ bf16 g_act_h[(size_t)cfg::T * cfg::F], g_act_l[(size_t)cfg::T * cfg::F];
// split weights, [N,K] row-major bf16 hi/lo
__device__ bf16 g_wqkv_h[(size_t)3 * cfg::D * cfg::D], g_wqkv_l[(size_t)3 * cfg::D * cfg::D];
__device__ bf16 g_wo_h[(size_t)cfg::D * cfg::D],       g_wo_l[(size_t)cfg::D * cfg::D];
__device__ bf16 g_wg_h[(size_t)cfg::D * cfg::F],       g_wg_l[(size_t)cfg::D * cfg::F];
__device__ bf16 g_wu_h[(size_t)cfg::D * cfg::F],       g_wu_l[(size_t)cfg::D * cfg::F];
__device__ bf16 g_wd_h[(size_t)cfg::F * cfg::D],       g_wd_l[(size_t)cfg::F * cfg::D];
__device__ bf16 g_mem_h[(size_t)cfg::M * cfg::D],      g_mem_l[(size_t)cfg::M * cfg::D];

// ==================== helpers ====================
__device__ __forceinline__ uint32_t smem_u32(const void* p) {
    uint32_t a;
    asm("{ .reg .u64 t; cvta.to.shared.u64 t, %1; cvt.u32.u64 %0, t; }" : "=r"(a) : "l"(p));
    return a;
}
__device__ __forceinline__ uint32_t fmono(float f) {
    uint32_t u = __float_as_uint(f);
    return (u & 0x80000000u) ? ~u : (u | 0x80000000u);
}
__device__ __forceinline__ void split1(float x, bf16& h, bf16& l) {
    h = __float2bfloat16(x);
    l = __float2bfloat16(x - __bfloat162float(h));
}

#define CP16(d, s) asm volatile("cp.async.cg.shared.global [%0], [%1], 16;" :: "r"(d), "l"(s) : "memory")
#define CPCOMMIT() asm volatile("cp.async.commit_group;" ::: "memory")
#define CPWAIT1()  asm volatile("cp.async.wait_group 1;" ::: "memory")
#define CPWAIT0()  asm volatile("cp.async.wait_group 0;" ::: "memory")
#define LDSM4(r, a)                                                              \
    asm volatile("ldmatrix.sync.aligned.m8n8.x4.shared.b16 {%0,%1,%2,%3}, [%4];" \
        : "=r"((r)[0]), "=r"((r)[1]), "=r"((r)[2]), "=r"((r)[3]) : "r"(a))
#define MMA(c, a, b0, b1)                                                        \
    asm volatile("mma.sync.aligned.m16n8k16.row.col.f32.bf16.bf16.f32 "          \
        "{%0,%1,%2,%3},{%4,%5,%6,%7},{%8,%9},{%0,%1,%2,%3};"                     \
        : "+f"((c)[0]), "+f"((c)[1]), "+f"((c)[2]), "+f"((c)[3])                 \
        : "r"((a)[0]), "r"((a)[1]), "r"((a)[2]), "r"((a)[3]), "r"(b0), "r"(b1))

// ==================== split-bf16 3-pass mma.sync GEMM ====================
// C[128x128 tile] = (Ah+Al)[M,K] @ (Bh+Bl)[N,K]^T, dropping Al*Bl.
// Smem: 128 rows x 32 k bf16 = 64B rows, XOR swizzle (seg ^ ((row>>1)&3)).
// 3-stage cp.async pipeline, one __syncthreads per chunk.
// EPI: 0 store fp32, 1 C=Res+acc fp32, 2 Ch/Cl = split(silu(Res)*acc), 3 row-argmax.
constexpr int TILEB = 128 * 64;          // 8192
constexpr int STAGEB = 4 * TILEB;        // 32768 (Ah, Al, Bh, Bl)
constexpr int GEMM_SMEM = 3 * STAGEB;    // 98304

template<int EPI>
__global__ __launch_bounds__(256, 2)
void gemm_tc(const bf16* __restrict__ Ah_, const bf16* __restrict__ Al_,
             const bf16* __restrict__ Bh_, const bf16* __restrict__ Bl_,
             const float* __restrict__ Res, float* __restrict__ C,
             bf16* __restrict__ Ch, bf16* __restrict__ Cl,
             unsigned long long* __restrict__ argout, int Nc, int K) {
    extern __shared__ char dsm[];
    const uint32_t sb = smem_u32(dsm);
    const int tid = threadIdx.x, lane = tid & 31, warp = tid >> 5;
    const int wm = warp & 3, wn = warp >> 2;
    const int brow = blockIdx.y << 7, bcol = blockIdx.x << 7;

    // ---- cp.async src/dst (thread -> 2 rows x 1 seg per tile) ----
    const int r0 = tid >> 2, sg = tid & 3;
    const size_t rowK = (size_t)K * sizeof(bf16);
    const char* gAh = (const char*)Ah_ + (size_t)(brow + r0) * rowK + sg * 16;
    const char* gAl = (const char*)Al_ + (size_t)(brow + r0) * rowK + sg * 16;
    const char* gBh = (const char*)Bh_ + (size_t)(bcol + r0) * rowK + sg * 16;
    const char* gBl = (const char*)Bl_ + (size_t)(bcol + r0) * rowK + sg * 16;
    const size_t half = 64 * rowK;
    const uint32_t d0 = (uint32_t)(r0 * 64 + ((sg ^ ((r0 >> 1) & 3)) << 4));
    const uint32_t d1 = d0 + 64 * 64;

#define ISSUE(ch) do {                                                           \
    uint32_t sd = sb + (uint32_t)((ch) % 3) * STAGEB;                            \
    size_t go = (size_t)(ch) * 64;                                               \
    CP16(sd + d0,             gAh + go); CP16(sd + d1,             gAh + half + go); \
    CP16(sd + TILEB + d0,     gAl + go); CP16(sd + TILEB + d1,     gAl + half + go); \
    CP16(sd + 2 * TILEB + d0, gBh + go); CP16(sd + 2 * TILEB + d1, gBh + half + go); \
    CP16(sd + 3 * TILEB + d0, gBl + go); CP16(sd + 3 * TILEB + d1, gBl + half + go); \
    CPCOMMIT();                                                                  \
} while (0)

    // ---- ldmatrix lane addressing (same lane->(row,kseg) map as padded version) ----
    const int rA = wm * 32 + (lane & 15);
    const int xa = (rA >> 1) & 3;
    const uint32_t aBase = (uint32_t)(rA * 64);
    const int rB = wn * 64 + ((lane >> 4) << 3) + (lane & 7);
    const int xb = ((lane & 7) >> 1) & 3;
    const uint32_t bBase = (uint32_t)(rB * 64);
    const int aSegSel = lane >> 4;         // 16B seg within k16 half
    const int bSegSel = (lane >> 3) & 1;

    float acc[64];
#pragma unroll
    for (int i = 0; i < 64; i++) acc[i] = 0.f;

    const int nch = K >> 5;
    ISSUE(0); ISSUE(1);
    for (int ch = 0; ch < nch; ch++) {
        if (ch + 1 < nch) CPWAIT1(); else CPWAIT0();
        __syncthreads();
        if (ch + 2 < nch) ISSUE(ch + 2);
        const uint32_t bb = sb + (uint32_t)(ch % 3) * STAGEB;
#pragma unroll
        for (int ks = 0; ks < 2; ks++) {
            uint32_t ah[2][4], al[2][4];
            const uint32_t a0 = bb + aBase + (uint32_t)((((ks << 1) + aSegSel) ^ xa) << 4);
            LDSM4(ah[0], a0);
            LDSM4(ah[1], a0 + 1024);                  // +16 rows
            LDSM4(al[0], a0 + TILEB);
            LDSM4(al[1], a0 + TILEB + 1024);
#pragma unroll
            for (int np = 0; np < 4; np++) {
                uint32_t bh[4], bl[4];
                const uint32_t b0a = bb + 2 * TILEB + bBase + (uint32_t)(np * 1024) +
                                     (uint32_t)((((ks << 1) + bSegSel) ^ xb) << 4);
                LDSM4(bh, b0a);
                LDSM4(bl, b0a + TILEB);
                float* c00 = acc + (0 * 8 + np * 2) * 4;
                float* c01 = acc + (0 * 8 + np * 2 + 1) * 4;
                float* c10 = acc + (1 * 8 + np * 2) * 4;
                float* c11 = acc + (1 * 8 + np * 2 + 1) * 4;
                MMA(c00, ah[0], bh[0], bh[1]); MMA(c01, ah[0], bh[2], bh[3]);
                MMA(c10, ah[1], bh[0], bh[1]); MMA(c11, ah[1], bh[2], bh[3]);
                MMA(c00, ah[0], bl[0], bl[1]); MMA(c01, ah[0], bl[2], bl[3]);
                MMA(c10, ah[1], bl[0], bl[1]); MMA(c11, ah[1], bl[2], bl[3]);
                MMA(c00, al[0], bh[0], bh[1]); MMA(c01, al[0], bh[2], bh[3]);
                MMA(c10, al[1], bh[0], bh[1]); MMA(c11, al[1], bh[2], bh[3]);
            }
        }
    }
#undef ISSUE

    // ---- epilogue ----
    const int rq = lane >> 2, cp2 = (lane & 3) * 2;
    if (EPI == 3) {
#pragma unroll
        for (int mf = 0; mf < 2; mf++)
#pragma unroll
        for (int hh = 0; hh < 2; hh++) {
            const int row = brow + wm * 32 + mf * 16 + rq + hh * 8;
            float best = -3.4e38f; int bi = 0;
#pragma unroll
            for (int nf = 0; nf < 8; nf++)
#pragma unroll
            for (int c = 0; c < 2; c++) {
                float v = acc[(mf * 8 + nf) * 4 + hh * 2 + c];
                int col = bcol + wn * 64 + nf * 8 + cp2 + c;
                if (v > best) { best = v; bi = col; }
            }
            unsigned long long pk =
                ((unsigned long long)fmono(best) << 32) | (uint32_t)(~(uint32_t)bi);
            unsigned long long o1 = __shfl_xor_sync(0xffffffffu, pk, 1); if (o1 > pk) pk = o1;
            unsigned long long o2 = __shfl_xor_sync(0xffffffffu, pk, 2); if (o2 > pk) pk = o2;
            if ((lane & 3) == 0) atomicMax(argout + row, pk);
        }
    } else {
#pragma unroll
        for (int mf = 0; mf < 2; mf++)
#pragma unroll
        for (int hh = 0; hh < 2; hh++) {
            const int row = brow + wm * 32 + mf * 16 + rq + hh * 8;
            const size_t ro = (size_t)row * Nc + bcol + wn * 64 + cp2;
#pragma unroll
            for (int nf = 0; nf < 8; nf++) {
                const size_t o = ro + nf * 8;
                float v0 = acc[(mf * 8 + nf) * 4 + hh * 2];
                float v1 = acc[(mf * 8 + nf) * 4 + hh * 2 + 1];
                if (EPI == 1) {
                    float2 rr = *(const float2*)(Res + o);
                    v0 += rr.x; v1 += rr.y;
                    *(float2*)(C + o) = make_float2(v0, v1);
                } else if (EPI == 2) {
                    float2 g = *(const float2*)(Res + o);
                    v0 *= g.x / (1.f + __expf(-g.x));
                    v1 *= g.y / (1.f + __expf(-g.y));
                    bf16 h0, l0, h1, l1;
                    split1(v0, h0, l0); split1(v1, h1, l1);
                    *(__nv_bfloat162*)(Ch + o) = __halves2bfloat162(h0, h1);
                    *(__nv_bfloat162*)(Cl + o) = __halves2bfloat162(l0, l1);
                } else {
                    *(float2*)(C + o) = make_float2(v0, v1);
                }
            }
        }
    }
}

// ==================== fused all-weights transpose + split ====================
// [K,N] fp32 -> [N,K] bf16 hi/lo, 64x64 tiles, float4 reads, bf16x2 writes.
struct WConv { const float* src; bf16* dh; bf16* dl; int K; int N; int blkOff; };
struct WConvAll { WConv m[7]; };

__global__ __launch_bounds__(256)
void conv_weights(WConvAll P) {
    const int bid = blockIdx.x;
    int mi = 0;
#pragma unroll
    for (int i = 1; i < 7; i++) if (bid >= P.m[i].blkOff) mi = i;
    const WConv w = P.m[mi];
    const int id = bid - w.blkOff;
    const int ntn = w.N >> 6;
    const int n0 = (id % ntn) << 6, k0 = (id / ntn) << 6;

    __shared__ float t[64][65];
    const int tr = threadIdx.x >> 4, tc4 = (threadIdx.x & 15) << 2;
#pragma unroll
    for (int p = 0; p < 4; p++) {
        float4 v = *(const float4*)(w.src + (size_t)(k0 + tr + p * 16) * w.N + n0 + tc4);
        t[tr + p * 16][tc4] = v.x; t[tr + p * 16][tc4 + 1] = v.y;
        t[tr + p * 16][tc4 + 2] = v.z; t[tr + p * 16][tc4 + 3] = v.w;
    }
    __syncthreads();
    const int n = threadIdx.x >> 2, kq = (threadIdx.x & 3) << 4;
    const size_t ob = (size_t)(n0 + n) * w.K + k0 + kq;
#pragma unroll
    for (int j = 0; j < 16; j += 2) {
        float v0 = t[kq + j][n], v1 = t[kq + j + 1][n];
        bf16 h0, l0, h1, l1;
        split1(v0, h0, l0); split1(v1, h1, l1);
        *(__nv_bfloat162*)(w.dh + ob + j) = __halves2bfloat162(h0, h1);
        *(__nv_bfloat162*)(w.dl + ob + j) = __halves2bfloat162(l0, l1);
    }
}

// split-only (row-major pass-through), optionally zero nnpack
template<int INIT>
__global__ __launch_bounds__(256)
void split_only(const float* __restrict__ W, bf16* __restrict__ Oh,
                bf16* __restrict__ Ol, size_t n4) {
    size_t i = (size_t)blockIdx.x * 256 + threadIdx.x;
    if (INIT && i < (size_t)cfg::T) g_nnpack[i] = 0ull;
    if (i >= n4) return;
    float4 v = ((const float4*)W)[i];
    bf16 h0, l0, h1, l1, h2, l2, h3, l3;
    split1(v.x, h0, l0); split1(v.y, h1, l1);
    split1(v.z, h2, l2); split1(v.w, h3, l3);
    __nv_bfloat162 H0 = __halves2bfloat162(h0, h1), H1 = __halves2bfloat162(h2, h3);
    __nv_bfloat162 L0 = __halves2bfloat162(l0, l1), L1 = __halves2bfloat162(l2, l3);
    ((uint2*)Oh)[i] = make_uint2(*(uint32_t*)&H0, *(uint32_t*)&H1);
    ((uint2*)Ol)[i] = make_uint2(*(uint32_t*)&L0, *(uint32_t*)&L1);
}

// ==================== fused gather + gated L2 mix + RMSNorm1 (-> x1 hi/lo) ====================
__global__ __launch_bounds__(256)
void merge_rms1_kernel(const float* __restrict__ hs, const float* __restrict__ mem,
                       const float* __restrict__ gatel, const float* __restrict__ r1w) {
    const int t = blockIdx.x, tid = threadIdx.x;
    const uint32_t idx = ~(uint32_t)(g_nnpack[t] & 0xffffffffull);
    const float* h = hs + (size_t)t * cfg::D;
    const float* mr = mem + (size_t)idx * cfg::D;
    __shared__ float red[256], red2[256];
    float sh = 0.f, sm = 0.f;
    for (int d = tid; d < cfg::D; d += 256) {
        float a = h[d], bm = mr[d];
        sh += a * a; sm += bm * bm;
    }
    red[tid] = sh; red2[tid] = sm;
    __syncthreads();
    for (int s = 128; s; s >>= 1) {
        if (tid < s) { red[tid] += red[tid + s]; red2[tid] += red2[tid + s]; }
        __syncthreads();
    }
    const float nh = sqrtf(red[0]) + 1e-4f;
    const float nm = sqrtf(red2[0]) + 1e-4f;
    __syncthreads();
    float s2 = 0.f;
    for (int d = tid; d < cfg::D; d += 256) {
        float g = 1.f / (1.f + __expf(-gatel[d]));
        float mg = (g * h[d] / nh + (1.f - g) * mr[d] / nm) * nh;
        g_merged[(size_t)t * cfg::D + d] = mg;
        s2 += mg * mg;
    }
    red[tid] = s2;
    __syncthreads();
    for (int s = 128; s; s >>= 1) {
        if (tid < s) red[tid] += red[tid + s];
        __syncthreads();
    }
    const float rstd = rsqrtf(red[0] / cfg::D + 1e-6f);
    for (int d = tid; d < cfg::D; d += 256) {
        float v = g_merged[(size_t)t * cfg::D + d] * rstd * r1w[d];
        size_t o = (size_t)t * cfg::D + d;
        split1(v, g_x1_h[o], g_x1_l[o]);
    }
}

// ==================== RMSNorm2 (-> y hi/lo) ====================
__global__ __launch_bounds__(256)
void rmsnorm_kernel(const float* __restrict__ x, const float* __restrict__ w) {
    const int t = blockIdx.x, tid = threadIdx.x;
    const float* xp = x + (size_t)t * cfg::D;
    __shared__ float red[256];
    float s2 = 0.f;
    for (int d = tid; d < cfg::D; d += 256) { float v = xp[d]; s2 += v * v; }
    red[tid] = s2;
    __syncthreads();
    for (int s = 128; s; s >>= 1) {
        if (tid < s) red[tid] += red[tid + s];
        __syncthreads();
    }
    const float rstd = rsqrtf(red[0] / cfg::D + 1e-6f);
    for (int d = tid; d < cfg::D; d += 256) {
        float v = xp[d] * rstd * w[d];
        size_t o = (size_t)t * cfg::D + d;
        split1(v, g_y_h[o], g_y_l[o]);
    }
}

// ==================== RoPE (in-place on qkv [T, 3D]) ====================
__global__ __launch_bounds__(256)
void rope_kernel(const int* __restrict__ pos) {
    const int idx = blockIdx.x * 256 + threadIdx.x;
    if (idx >= cfg::T * cfg::H * 64) return;
    const int i = idx & 63;
    const int h = (idx >> 6) & (cfg::H - 1);
    const int t = idx >> 10;
    const float p = (float)pos[t];
    const float inv = expf(-0.14391156831212787f * (float)i);
    float sn, cs;
    sincosf(p * inv, &sn, &cs);
    const size_t base = (size_t)t * (3 * cfg::D) + h * cfg::HD;
    float q1 = g_qkv[base + i], q2 = g_qkv[base + i + 64];
    g_qkv[base + i]      = q1 * cs - q2 * sn;
    g_qkv[base + i + 64] = q2 * cs + q1 * sn;
    const size_t kb = base + cfg::D;
    float k1 = g_qkv[kb + i], k2 = g_qkv[kb + i + 64];
    g_qkv[kb + i]      = k1 * cs - k2 * sn;
    g_qkv[kb + i + 64] = k2 * cs + k1 * sn;
}

// ==================== causal attention (warp per q-row) -> ctx hi/lo ====================
__global__ __launch_bounds__(256)
void attn_kernel() {
    const int tid = threadIdx.x;
    const int warp = tid >> 5, lane = tid & 31;
    const int b = blockIdx.z, h = blockIdx.y;
    const int qrow = blockIdx.x * 8 + warp;
    __shared__ float Ksm[32][128];
    __shared__ float Vsm[32][128];
    const size_t qb = (size_t)(b * cfg::S + qrow) * (3 * cfg::D) + h * cfg::HD;
    float qf[4];
#pragma unroll
    for (int i = 0; i < 4; i++) qf[i] = g_qkv[qb + lane + 32 * i];
    float m = -INFINITY, l = 0.f;
    float acc[4] = {0.f, 0.f, 0.f, 0.f};
    const int nk = blockIdx.x * 8 + 8;
    const float scale = 0.08838834764831845f;

    for (int s0 = 0; s0 < nk; s0 += 32) {
        __syncthreads();
        for (int i = tid; i < 32 * 128; i += 256) {
            int r = i >> 7, c = i & 127;
            size_t off = (size_t)(b * cfg::S + s0 + r) * (3 * cfg::D) + h * cfg::HD + c;
            Ksm[r][c] = g_qkv[off + cfg::D];
            Vsm[r][c] = g_qkv[off + 2 * cfg::D];
        }
        __syncthreads();
        const int lim = min(32, qrow + 1 - s0);
        for (int kk = 0; kk < lim; kk++) {
            float p = qf[0] * Ksm[kk][lane]      + qf[1] * Ksm[kk][lane + 32] +
                      qf[2] * Ksm[kk][lane + 64] + qf[3] * Ksm[kk][lane + 96];
#pragma unroll
            for (int o = 16; o; o >>= 1) p += __shfl_xor_sync(0xffffffffu, p, o);
            p *= scale;
            float mn = fmaxf(m, p);
            float corr = __expf(m - mn);
            float w = __expf(p - mn);
            l = l * corr + w;
#pragma unroll
            for (int i = 0; i < 4; i++) acc[i] = acc[i] * corr + w * Vsm[kk][lane + 32 * i];
            m = mn;
        }
    }
    const float inv = 1.f / l;
    const size_t ob = (size_t)(b * cfg::S + qrow) * cfg::D + h * cfg::HD;
#pragma unroll
    for (int i = 0; i < 4; i++) {
        float v = acc[i] * inv;
        split1(v, g_ctx_h[ob + lane + 32 * i], g_ctx_l[ob + lane + 32 * i]);
    }
}

// ==================== launch ====================
extern "C" void kernel_launch(void* const* d_in, const int* in_sizes, int n_in,
                              void* d_out, int out_size) {
    using namespace cfg;
    const float* hs    = (const float*)d_in[0];
    const int*   pos   = (const int*)d_in[1];
    const float* mem   = (const float*)d_in[2];
    const float* gatel = (const float*)d_in[3];
    const float* wq    = (const float*)d_in[4];
    const float* wk    = (const float*)d_in[5];
    const float* wv    = (const float*)d_in[6];
    const float* wo    = (const float*)d_in[7];
    const float* wg    = (const float*)d_in[8];
    const float* wu    = (const float*)d_in[9];
    const float* wd    = (const float*)d_in[10];
    const float* r1w   = (const float*)d_in[11];
    const float* r2w   = (const float*)d_in[12];
    float* out = (float*)d_out;

    static bool attr_set = false;
    if (!attr_set) {
        cudaFuncSetAttribute(gemm_tc<0>, cudaFuncAttributeMaxDynamicSharedMemorySize, GEMM_SMEM);
        cudaFuncSetAttribute(gemm_tc<1>, cudaFuncAttributeMaxDynamicSharedMemorySize, GEMM_SMEM);
        cudaFuncSetAttribute(gemm_tc<2>, cudaFuncAttributeMaxDynamicSharedMemorySize, GEMM_SMEM);
        cudaFuncSetAttribute(gemm_tc<3>, cudaFuncAttributeMaxDynamicSharedMemorySize, GEMM_SMEM);
        attr_set = true;
    }

    float *p_merged, *p_qkv, *p_x2, *p_gate;
    unsigned long long* p_nn;
    bf16 *p_hs_h, *p_hs_l, *p_x1_h, *p_x1_l, *p_ctx_h, *p_ctx_l, *p_y_h, *p_y_l;
    bf16 *p_act_h, *p_act_l;
    bf16 *p_wqkv_h, *p_wqkv_l, *p_wo_h, *p_wo_l, *p_wg_h, *p_wg_l;
    bf16 *p_wu_h, *p_wu_l, *p_wd_h, *p_wd_l, *p_mem_h, *p_mem_l;
    cudaGetSymbolAddress((void**)&p_merged, g_merged);
    cudaGetSymbolAddress((void**)&p_qkv, g_qkv);
    cudaGetSymbolAddress((void**)&p_x2, g_x2);
    cudaGetSymbolAddress((void**)&p_gate, g_gate);
    cudaGetSymbolAddress((void**)&p_nn, g_nnpack);
    cudaGetSymbolAddress((void**)&p_hs_h, g_hs_h);
    cudaGetSymbolAddress((void**)&p_hs_l, g_hs_l);
    cudaGetSymbolAddress((void**)&p_x1_h, g_x1_h);
    cudaGetSymbolAddress((void**)&p_x1_l, g_x1_l);
    cudaGetSymbolAddress((void**)&p_ctx_h, g_ctx_h);
    cudaGetSymbolAddress((void**)&p_ctx_l, g_ctx_l);
    cudaGetSymbolAddress((void**)&p_y_h, g_y_h);
    cudaGetSymbolAddress((void**)&p_y_l, g_y_l);
    cudaGetSymbolAddress((void**)&p_act_h, g_act_h);
    cudaGetSymbolAddress((void**)&p_act_l, g_act_l);
    cudaGetSymbolAddress((void**)&p_wqkv_h, g_wqkv_h);
    cudaGetSymbolAddress((void**)&p_wqkv_l, g_wqkv_l);
    cudaGetSymbolAddress((void**)&p_wo_h, g_wo_h);
    cudaGetSymbolAddress((void**)&p_wo_l, g_wo_l);
    cudaGetSymbolAddress((void**)&p_wg_h, g_wg_h);
    cudaGetSymbolAddress((void**)&p_wg_l, g_wg_l);
    cudaGetSymbolAddress((void**)&p_wu_h, g_wu_h);
    cudaGetSymbolAddress((void**)&p_wu_l, g_wu_l);
    cudaGetSymbolAddress((void**)&p_wd_h, g_wd_h);
    cudaGetSymbolAddress((void**)&p_wd_l, g_wd_l);
    cudaGetSymbolAddress((void**)&p_mem_h, g_mem_h);
    cudaGetSymbolAddress((void**)&p_mem_l, g_mem_l);

    const dim3 blk(256);

    // ---- prep (3 launches) ----
    const int tDD = (D / 64) * (D / 64);       // 1024
    const int tDF = (F / 64) * (D / 64);       // 4096
    WConvAll P;
    P.m[0] = {wq, p_wqkv_h,                    p_wqkv_l,                    D, D, 0};
    P.m[1] = {wk, p_wqkv_h + (size_t)D * D,    p_wqkv_l + (size_t)D * D,    D, D, tDD};
    P.m[2] = {wv, p_wqkv_h + 2 * (size_t)D * D, p_wqkv_l + 2 * (size_t)D * D, D, D, 2 * tDD};
    P.m[3] = {wo, p_wo_h, p_wo_l, D, D, 3 * tDD};
    P.m[4] = {wg, p_wg_h, p_wg_l, D, F, 4 * tDD};
    P.m[5] = {wu, p_wu_h, p_wu_l, D, F, 4 * tDD + tDF};
    P.m[6] = {wd, p_wd_h, p_wd_l, F, D, 4 * tDD + 2 * tDF};
    const int nblk = 4 * tDD + 2 * tDF + tDD;  // wd has (D/64)*(F/64) = tDF? no: N=D,K=F -> (D/64)*(F/64)=4096
    conv_weights<<<4 * tDD + 3 * tDF, blk>>>(P);
    (void)nblk;
    split_only<0><<<(int)(((size_t)M * D / 4 + 255) / 256), blk>>>(mem, p_mem_h, p_mem_l, (size_t)M * D / 4);
    split_only<1><<<(int)(((size_t)T * D / 4 + 255) / 256), blk>>>(hs, p_hs_h, p_hs_l, (size_t)T * D / 4);

    // ---- 1) kNN scores GEMM with fused argmax ----
    gemm_tc<3><<<dim3(M / 128, T / 128), blk, GEMM_SMEM>>>(
        p_hs_h, p_hs_l, p_mem_h, p_mem_l, nullptr, nullptr, nullptr, nullptr, p_nn, M, D);

    // ---- 2) gated merge + RMSNorm1 -> x1 hi/lo ----
    merge_rms1_kernel<<<T, blk>>>(hs, mem, gatel, r1w);

    // ---- 3) fused QKV projection [T, 3D] fp32  (ncu -s 5 lands here) ----
    gemm_tc<0><<<dim3(3 * D / 128, T / 128), blk, GEMM_SMEM>>>(
        p_x1_h, p_x1_l, p_wqkv_h, p_wqkv_l, nullptr, p_qkv, nullptr, nullptr, nullptr, 3 * D, D);

    // ---- 4) RoPE ----
    rope_kernel<<<(T * H * 64 + 255) / 256, blk>>>(pos);

    // ---- 5) causal attention -> ctx hi/lo ----
    attn_kernel<<<dim3(S / 8, H, B), blk>>>();

    // ---- 6) O projection + residual -> x2 fp32 ----
    gemm_tc<1><<<dim3(D / 128, T / 128), blk, GEMM_SMEM>>>(
        p_ctx_h, p_ctx_l, p_wo_h, p_wo_l, p_merged, p_x2, nullptr, nullptr, nullptr, D, D);

    // ---- 7) RMSNorm2 -> y hi/lo ----
    rmsnorm_kernel<<<T, blk>>>(p_x2, r2w);

    // ---- 8) MLP: gate fp32; up w/ silu epi -> act hi/lo; down + residual -> out ----
    gemm_tc<0><<<dim3(F / 128, T / 128), blk, GEMM_SMEM>>>(
        p_y_h, p_y_l, p_wg_h, p_wg_l, nullptr, p_gate, nullptr, nullptr, nullptr, F, D);
    gemm_tc<2><<<dim3(F / 128, T / 128), blk, GEMM_SMEM>>>(
        p_y_h, p_y_l, p_wu_h, p_wu_l, p_gate, nullptr, p_act_h, p_act_l, nullptr, F, D);
    gemm_tc<1><<<dim3(D / 128, T / 128), blk, GEMM_SMEM>>>(
        p_act_h, p_act_l, p_wd_h, p_wd_l, p_x2, out, nullptr, nullptr, nullptr, D, F);
}